// round 3
// baseline (speedup 1.0000x reference)
#include <cuda_runtime.h>
#include <cuda_bf16.h>
#include <cstdint>

// Problem constants
#define BB 32
#define NS 262144
#define HH 256
#define WW 256
#define HWSZ (HH * WW)

// Order-encoded bounds, split by polarity so cudaMemsetAsync can initialize:
// g_minenc bytes 0xFF == encoded +inf (identity for min)
// g_maxenc bytes 0x00 == encoded -inf (identity for max)
// layout: [b][0]=x, [b][1]=y
__device__ unsigned g_minenc[BB][2];
__device__ unsigned g_maxenc[BB][2];

// Order-preserving float<->uint encoding
__device__ __forceinline__ unsigned f2o(float f) {
    unsigned u = __float_as_uint(f);
    return (u & 0x80000000u) ? ~u : (u | 0x80000000u);
}
__device__ __forceinline__ float o2f(unsigned u) {
    return __uint_as_float((u & 0x80000000u) ? (u & 0x7fffffffu) : ~u);
}

// grid = (SEGS, BB), block = 256. Full-chip DRAM-bound reduction.
constexpr int SEGS = 16;

__global__ __launch_bounds__(256) void minmax_kernel(const float* __restrict__ spatial) {
    const int b = blockIdx.y;
    const int seg_elems = HWSZ / SEGS;                 // 4096 floats
    const float* base = spatial + (size_t)b * 2 * HWSZ + (size_t)blockIdx.x * seg_elems;
    const float4* vx = reinterpret_cast<const float4*>(base);
    const float4* vy = reinterpret_cast<const float4*>(base + HWSZ);
    const int nvec = seg_elems / 4;                    // 1024

    float xmn = 3.4e38f, xmx = -3.4e38f, ymn = 3.4e38f, ymx = -3.4e38f;

    for (int i = threadIdx.x; i < nvec; i += blockDim.x) {
        float4 a = vx[i];
        xmn = fminf(xmn, fminf(fminf(a.x, a.y), fminf(a.z, a.w)));
        xmx = fmaxf(xmx, fmaxf(fmaxf(a.x, a.y), fmaxf(a.z, a.w)));
        float4 c = vy[i];
        ymn = fminf(ymn, fminf(fminf(c.x, c.y), fminf(c.z, c.w)));
        ymx = fmaxf(ymx, fmaxf(fmaxf(c.x, c.y), fmaxf(c.z, c.w)));
    }

    #pragma unroll
    for (int off = 16; off > 0; off >>= 1) {
        xmn = fminf(xmn, __shfl_xor_sync(0xFFFFFFFFu, xmn, off));
        xmx = fmaxf(xmx, __shfl_xor_sync(0xFFFFFFFFu, xmx, off));
        ymn = fminf(ymn, __shfl_xor_sync(0xFFFFFFFFu, ymn, off));
        ymx = fmaxf(ymx, __shfl_xor_sync(0xFFFFFFFFu, ymx, off));
    }

    if ((threadIdx.x & 31) == 0) {
        atomicMin(&g_minenc[b][0], f2o(xmn));
        atomicMax(&g_maxenc[b][0], f2o(xmx));
        atomicMin(&g_minenc[b][1], f2o(ymn));
        atomicMax(&g_maxenc[b][1], f2o(ymx));
    }
}

// Scatter: accumulate ONLY masked point_rates; gia multiply deferred.
constexpr int TPB = 256;
constexpr int IT  = 8;

__global__ __launch_bounds__(TPB) void scatter_kernel(
    const float*  __restrict__ point_rates,
    const float2* __restrict__ coords,
    float*        __restrict__ out)
{
    const int b = blockIdx.y;
    const float xmin = o2f(g_minenc[b][0]);
    const float xmax = o2f(g_maxenc[b][0]);
    const float ymin = o2f(g_minenc[b][1]);
    const float ymax = o2f(g_maxenc[b][1]);
    const float dx = __fsub_rn(xmax, xmin);
    const float dy = __fsub_rn(ymax, ymin);

    const float* pr = point_rates + (size_t)b * NS;
    float* ob = out + (size_t)b * HWSZ;

    const int base = blockIdx.x * (TPB * IT) + threadIdx.x;

    #pragma unroll
    for (int j = 0; j < IT; j++) {
        const int i = base + j * TPB;
        const float2 c = coords[i];
        const float rate = pr[i];
        const bool iv = (c.x >= xmin) && (c.x <= xmax) && (c.y >= ymin) && (c.y <= ymax);
        // Match reference bit-exactly: strict IEEE rn sub/div/mul, then
        // round-half-even (== jnp.round) before clip.
        const float nx = __fdiv_rn(__fsub_rn(c.x, xmin), dx);
        const float ny = __fdiv_rn(__fsub_rn(c.y, ymin), dy);
        int px = __float2int_rn(__fmul_rn(nx, 255.0f));
        int py = __float2int_rn(__fmul_rn(ny, 255.0f));
        px = min(max(px, 0), WW - 1);
        py = min(max(py, 0), HH - 1);
        if (iv) {
            atomicAdd(&ob[py * WW + px], rate);   // RED.ADD, no return
        }
    }
}

// Streaming finalize: out[i] = rate_sum[i] * gia[i].
constexpr int MTPB = 256;
constexpr int MIT  = 4;

__global__ __launch_bounds__(MTPB) void mul_kernel(const float4* __restrict__ gia,
                                                   float4* __restrict__ out,
                                                   int n4)
{
    int i = blockIdx.x * MTPB + threadIdx.x;
    const int stride = gridDim.x * MTPB;
    for (; i < n4; i += stride) {
        float4 o = out[i];
        float4 g = gia[i];
        o.x = __fmul_rn(o.x, g.x);
        o.y = __fmul_rn(o.y, g.y);
        o.z = __fmul_rn(o.z, g.z);
        o.w = __fmul_rn(o.w, g.w);
        out[i] = o;
    }
}

extern "C" void kernel_launch(void* const* d_in, const int* in_sizes, int n_in,
                              void* d_out, int out_size)
{
    const float*  point_rates = (const float*)d_in[0];   // (B, NS)
    const float*  spatial     = (const float*)d_in[1];   // (B, 2, H, W)
    const float*  gia         = (const float*)d_in[2];   // (B, H, W)
    const float2* coords      = (const float2*)d_in[3];  // (NS, 2)
    float* out = (float*)d_out;                          // (B, 1, H, W)

    // Initialize encoded bounds via memset (0xFF = +inf enc, 0x00 = -inf enc)
    void* p_min = nullptr;
    void* p_max = nullptr;
    cudaGetSymbolAddress(&p_min, g_minenc);
    cudaGetSymbolAddress(&p_max, g_maxenc);
    cudaMemsetAsync(p_min, 0xFF, sizeof(unsigned) * BB * 2, 0);
    cudaMemsetAsync(p_max, 0x00, sizeof(unsigned) * BB * 2, 0);

    // Zero the accumulation field
    cudaMemsetAsync(d_out, 0, (size_t)out_size * sizeof(float), 0);

    // Per-batch min/max, full-chip
    dim3 mg(SEGS, BB);
    minmax_kernel<<<mg, 256>>>(spatial);

    // Scatter-add of masked rates
    dim3 sg(NS / (TPB * IT), BB);
    scatter_kernel<<<sg, TPB>>>(point_rates, coords, out);

    // Finalize: multiply by gia
    const int n4 = (BB * HWSZ) / 4;
    mul_kernel<<<n4 / (MTPB * MIT), MTPB>>>((const float4*)gia, (float4*)out, n4);
}

// round 4
// speedup vs baseline: 1.1152x; 1.1152x over previous
#include <cuda_runtime.h>
#include <cuda_bf16.h>
#include <cstdint>

// Problem constants
#define BB 32
#define NS 262144
#define HH 256
#define WW 256
#define HWSZ (HH * WW)

constexpr int SEGS = 16;

// Per-(batch, segment) partial bounds: x = xmin, y = xmax, z = ymin, w = ymax.
// Written unconditionally by minmax blocks (no init needed, no atomics).
__device__ float4 g_part[BB][SEGS];

// grid = (SEGS, BB), block = 256. Each thread: exactly 4 float4 per channel.
__global__ __launch_bounds__(256) void minmax_kernel(const float* __restrict__ spatial) {
    const int b = blockIdx.y;
    const int seg_elems = HWSZ / SEGS;                 // 4096 floats
    const float* base = spatial + (size_t)b * 2 * HWSZ + (size_t)blockIdx.x * seg_elems;
    const float4* vx = reinterpret_cast<const float4*>(base);
    const float4* vy = reinterpret_cast<const float4*>(base + HWSZ);

    // 1024 float4 per channel / 256 threads = 4 each. Front-batch all 8 loads.
    float4 ax[4], ay[4];
    #pragma unroll
    for (int j = 0; j < 4; j++) ax[j] = vx[threadIdx.x + j * 256];
    #pragma unroll
    for (int j = 0; j < 4; j++) ay[j] = vy[threadIdx.x + j * 256];

    float xmn = 3.4e38f, xmx = -3.4e38f, ymn = 3.4e38f, ymx = -3.4e38f;
    #pragma unroll
    for (int j = 0; j < 4; j++) {
        xmn = fminf(xmn, fminf(fminf(ax[j].x, ax[j].y), fminf(ax[j].z, ax[j].w)));
        xmx = fmaxf(xmx, fmaxf(fmaxf(ax[j].x, ax[j].y), fmaxf(ax[j].z, ax[j].w)));
        ymn = fminf(ymn, fminf(fminf(ay[j].x, ay[j].y), fminf(ay[j].z, ay[j].w)));
        ymx = fmaxf(ymx, fmaxf(fmaxf(ay[j].x, ay[j].y), fmaxf(ay[j].z, ay[j].w)));
    }

    #pragma unroll
    for (int off = 16; off > 0; off >>= 1) {
        xmn = fminf(xmn, __shfl_xor_sync(0xFFFFFFFFu, xmn, off));
        xmx = fmaxf(xmx, __shfl_xor_sync(0xFFFFFFFFu, xmx, off));
        ymn = fminf(ymn, __shfl_xor_sync(0xFFFFFFFFu, ymn, off));
        ymx = fmaxf(ymx, __shfl_xor_sync(0xFFFFFFFFu, ymx, off));
    }

    // cross-warp combine in smem (8 warps)
    __shared__ float4 s[8];
    const int wid = threadIdx.x >> 5;
    const int lid = threadIdx.x & 31;
    if (lid == 0) s[wid] = make_float4(xmn, xmx, ymn, ymx);
    __syncthreads();
    if (threadIdx.x == 0) {
        float4 r = s[0];
        #pragma unroll
        for (int w = 1; w < 8; w++) {
            r.x = fminf(r.x, s[w].x);
            r.y = fmaxf(r.y, s[w].y);
            r.z = fminf(r.z, s[w].z);
            r.w = fmaxf(r.w, s[w].w);
        }
        g_part[b][blockIdx.x] = r;
    }
}

// Scatter: accumulate ONLY masked point_rates; gia multiply deferred.
// Prologue: one warp reduces the SEGS partials to final bounds.
constexpr int TPB = 256;
constexpr int IT  = 8;

__global__ __launch_bounds__(TPB) void scatter_kernel(
    const float*  __restrict__ point_rates,
    const float2* __restrict__ coords,
    float*        __restrict__ out)
{
    const int b = blockIdx.y;

    __shared__ float4 sb;   // xmin, xmax, ymin, ymax
    if (threadIdx.x < 32) {
        const int lid = threadIdx.x;
        float xmn = 3.4e38f, xmx = -3.4e38f, ymn = 3.4e38f, ymx = -3.4e38f;
        if (lid < SEGS) {
            float4 p = g_part[b][lid];
            xmn = p.x; xmx = p.y; ymn = p.z; ymx = p.w;
        }
        #pragma unroll
        for (int off = 8; off > 0; off >>= 1) {
            xmn = fminf(xmn, __shfl_xor_sync(0xFFFFFFFFu, xmn, off));
            xmx = fmaxf(xmx, __shfl_xor_sync(0xFFFFFFFFu, xmx, off));
            ymn = fminf(ymn, __shfl_xor_sync(0xFFFFFFFFu, ymn, off));
            ymx = fmaxf(ymx, __shfl_xor_sync(0xFFFFFFFFu, ymx, off));
        }
        if (lid == 0) sb = make_float4(xmn, xmx, ymn, ymx);
    }
    __syncthreads();

    const float xmin = sb.x, xmax = sb.y, ymin = sb.z, ymax = sb.w;
    const float dx = __fsub_rn(xmax, xmin);
    const float dy = __fsub_rn(ymax, ymin);

    const float* pr = point_rates + (size_t)b * NS;
    float* ob = out + (size_t)b * HWSZ;

    const int base = blockIdx.x * (TPB * IT) + threadIdx.x;

    #pragma unroll
    for (int j = 0; j < IT; j++) {
        const int i = base + j * TPB;
        const float2 c = coords[i];
        const float rate = pr[i];
        const bool iv = (c.x >= xmin) && (c.x <= xmax) && (c.y >= ymin) && (c.y <= ymax);
        // Match reference bit-exactly: strict IEEE rn sub/div/mul, then
        // round-half-even (== jnp.round) before clip.
        const float nx = __fdiv_rn(__fsub_rn(c.x, xmin), dx);
        const float ny = __fdiv_rn(__fsub_rn(c.y, ymin), dy);
        int px = __float2int_rn(__fmul_rn(nx, 255.0f));
        int py = __float2int_rn(__fmul_rn(ny, 255.0f));
        px = min(max(px, 0), WW - 1);
        py = min(max(py, 0), HH - 1);
        if (iv) {
            atomicAdd(&ob[py * WW + px], rate);   // RED.ADD, no return
        }
    }
}

// Streaming finalize: out[i] = rate_sum[i] * gia[i].
constexpr int MTPB = 256;
constexpr int MIT  = 4;

__global__ __launch_bounds__(MTPB) void mul_kernel(const float4* __restrict__ gia,
                                                   float4* __restrict__ out,
                                                   int n4)
{
    int i = blockIdx.x * MTPB + threadIdx.x;
    const int stride = gridDim.x * MTPB;
    for (; i < n4; i += stride) {
        float4 o = out[i];
        float4 g = gia[i];
        o.x = __fmul_rn(o.x, g.x);
        o.y = __fmul_rn(o.y, g.y);
        o.z = __fmul_rn(o.z, g.z);
        o.w = __fmul_rn(o.w, g.w);
        out[i] = o;
    }
}

extern "C" void kernel_launch(void* const* d_in, const int* in_sizes, int n_in,
                              void* d_out, int out_size)
{
    const float*  point_rates = (const float*)d_in[0];   // (B, NS)
    const float*  spatial     = (const float*)d_in[1];   // (B, 2, H, W)
    const float*  gia         = (const float*)d_in[2];   // (B, H, W)
    const float2* coords      = (const float2*)d_in[3];  // (NS, 2)
    float* out = (float*)d_out;                          // (B, 1, H, W)

    // Zero the accumulation field (single memset node)
    cudaMemsetAsync(d_out, 0, (size_t)out_size * sizeof(float), 0);

    // Per-batch min/max partials, full-chip, no atomics, no init
    dim3 mg(SEGS, BB);
    minmax_kernel<<<mg, 256>>>(spatial);

    // Scatter-add of masked rates (reduces partials in prologue)
    dim3 sg(NS / (TPB * IT), BB);
    scatter_kernel<<<sg, TPB>>>(point_rates, coords, out);

    // Finalize: multiply by gia
    const int n4 = (BB * HWSZ) / 4;
    mul_kernel<<<n4 / (MTPB * MIT), MTPB>>>((const float4*)gia, (float4*)out, n4);
}

// round 5
// speedup vs baseline: 1.1512x; 1.0322x over previous
#include <cuda_runtime.h>
#include <cuda_bf16.h>
#include <cstdint>

// Problem constants
#define BB 32
#define NS 262144
#define HH 256
#define WW 256
#define HWSZ (HH * WW)

constexpr int SEGS = 16;

// Per-(batch, segment) partial bounds: x = xmin, y = xmax, z = ymin, w = ymax.
__device__ float4 g_part[BB][SEGS];

// grid = (SEGS, BB), block = 256. Computes partial min/max AND zeroes a slice
// of the output field (replaces the cudaMemsetAsync graph node).
__global__ __launch_bounds__(256) void minmax_kernel(const float* __restrict__ spatial,
                                                     float4* __restrict__ out4) {
    const int b = blockIdx.y;
    const int seg_elems = HWSZ / SEGS;                 // 4096 floats
    const float* base = spatial + (size_t)b * 2 * HWSZ + (size_t)blockIdx.x * seg_elems;
    const float4* vx = reinterpret_cast<const float4*>(base);
    const float4* vy = reinterpret_cast<const float4*>(base + HWSZ);

    // 1024 float4 per channel / 256 threads = 4 each. Front-batch all 8 loads.
    float4 ax[4], ay[4];
    #pragma unroll
    for (int j = 0; j < 4; j++) ax[j] = vx[threadIdx.x + j * 256];
    #pragma unroll
    for (int j = 0; j < 4; j++) ay[j] = vy[threadIdx.x + j * 256];

    float xmn = 3.4e38f, xmx = -3.4e38f, ymn = 3.4e38f, ymx = -3.4e38f;
    #pragma unroll
    for (int j = 0; j < 4; j++) {
        xmn = fminf(xmn, fminf(fminf(ax[j].x, ax[j].y), fminf(ax[j].z, ax[j].w)));
        xmx = fmaxf(xmx, fmaxf(fmaxf(ax[j].x, ax[j].y), fmaxf(ax[j].z, ax[j].w)));
        ymn = fminf(ymn, fminf(fminf(ay[j].x, ay[j].y), fminf(ay[j].z, ay[j].w)));
        ymx = fmaxf(ymx, fmaxf(fmaxf(ay[j].x, ay[j].y), fmaxf(ay[j].z, ay[j].w)));
    }

    // Zero this block's slice of the output field:
    // 2M floats / 512 blocks = 4096 floats = 1024 float4 per block.
    {
        const size_t blk = (size_t)b * SEGS + blockIdx.x;       // 0..511
        float4* oz = out4 + blk * 1024;
        const float4 z = make_float4(0.f, 0.f, 0.f, 0.f);
        #pragma unroll
        for (int j = 0; j < 4; j++) oz[threadIdx.x + j * 256] = z;
    }

    #pragma unroll
    for (int off = 16; off > 0; off >>= 1) {
        xmn = fminf(xmn, __shfl_xor_sync(0xFFFFFFFFu, xmn, off));
        xmx = fmaxf(xmx, __shfl_xor_sync(0xFFFFFFFFu, xmx, off));
        ymn = fminf(ymn, __shfl_xor_sync(0xFFFFFFFFu, ymn, off));
        ymx = fmaxf(ymx, __shfl_xor_sync(0xFFFFFFFFu, ymx, off));
    }

    __shared__ float4 s[8];
    const int wid = threadIdx.x >> 5;
    const int lid = threadIdx.x & 31;
    if (lid == 0) s[wid] = make_float4(xmn, xmx, ymn, ymx);
    __syncthreads();
    if (threadIdx.x == 0) {
        float4 r = s[0];
        #pragma unroll
        for (int w = 1; w < 8; w++) {
            r.x = fminf(r.x, s[w].x);
            r.y = fmaxf(r.y, s[w].y);
            r.z = fminf(r.z, s[w].z);
            r.w = fmaxf(r.w, s[w].w);
        }
        g_part[b][blockIdx.x] = r;
    }
}

// Scatter: accumulate ONLY masked point_rates; gia multiply deferred.
constexpr int TPB = 256;
constexpr int IT  = 16;

__global__ __launch_bounds__(TPB) void scatter_kernel(
    const float*  __restrict__ point_rates,
    const float2* __restrict__ coords,
    float*        __restrict__ out)
{
    const int b = blockIdx.y;
    const float* pr = point_rates + (size_t)b * NS;
    float* ob = out + (size_t)b * HWSZ;

    const int base = blockIdx.x * (TPB * IT) + threadIdx.x;

    // Issue ALL payload loads first so they're in flight while the bounds
    // prologue resolves (L2 hits, ~250cyc). BAR does not block pending LDG->reg.
    float2 c[IT];
    float  rate[IT];
    #pragma unroll
    for (int j = 0; j < IT; j++) c[j] = coords[base + j * TPB];
    #pragma unroll
    for (int j = 0; j < IT; j++) rate[j] = pr[base + j * TPB];

    // Bounds prologue: one warp reduces the SEGS partials.
    __shared__ float4 sb;
    if (threadIdx.x < 32) {
        const int lid = threadIdx.x;
        float xmn = 3.4e38f, xmx = -3.4e38f, ymn = 3.4e38f, ymx = -3.4e38f;
        if (lid < SEGS) {
            float4 p = g_part[b][lid];
            xmn = p.x; xmx = p.y; ymn = p.z; ymx = p.w;
        }
        #pragma unroll
        for (int off = 8; off > 0; off >>= 1) {
            xmn = fminf(xmn, __shfl_xor_sync(0xFFFFFFFFu, xmn, off));
            xmx = fmaxf(xmx, __shfl_xor_sync(0xFFFFFFFFu, xmx, off));
            ymn = fminf(ymn, __shfl_xor_sync(0xFFFFFFFFu, ymn, off));
            ymx = fmaxf(ymx, __shfl_xor_sync(0xFFFFFFFFu, ymx, off));
        }
        if (lid == 0) sb = make_float4(xmn, xmx, ymn, ymx);
    }
    __syncthreads();

    const float xmin = sb.x, xmax = sb.y, ymin = sb.z, ymax = sb.w;
    const float dx = __fsub_rn(xmax, xmin);
    const float dy = __fsub_rn(ymax, ymin);

    #pragma unroll
    for (int j = 0; j < IT; j++) {
        const bool iv = (c[j].x >= xmin) && (c[j].x <= xmax) &&
                        (c[j].y >= ymin) && (c[j].y <= ymax);
        // Match reference bit-exactly: strict IEEE rn sub/div/mul, then
        // round-half-even (== jnp.round) before clip.
        const float nx = __fdiv_rn(__fsub_rn(c[j].x, xmin), dx);
        const float ny = __fdiv_rn(__fsub_rn(c[j].y, ymin), dy);
        int px = __float2int_rn(__fmul_rn(nx, 255.0f));
        int py = __float2int_rn(__fmul_rn(ny, 255.0f));
        px = min(max(px, 0), WW - 1);
        py = min(max(py, 0), HH - 1);
        if (iv) {
            atomicAdd(&ob[py * WW + px], rate[j]);   // RED.ADD, no return
        }
    }
}

// Streaming finalize: out[i] = rate_sum[i] * gia[i].
constexpr int MTPB = 256;
constexpr int MIT  = 4;

__global__ __launch_bounds__(MTPB) void mul_kernel(const float4* __restrict__ gia,
                                                   float4* __restrict__ out,
                                                   int n4)
{
    int i = blockIdx.x * MTPB + threadIdx.x;
    const int stride = gridDim.x * MTPB;
    for (; i < n4; i += stride) {
        float4 o = out[i];
        float4 g = gia[i];
        o.x = __fmul_rn(o.x, g.x);
        o.y = __fmul_rn(o.y, g.y);
        o.z = __fmul_rn(o.z, g.z);
        o.w = __fmul_rn(o.w, g.w);
        out[i] = o;
    }
}

extern "C" void kernel_launch(void* const* d_in, const int* in_sizes, int n_in,
                              void* d_out, int out_size)
{
    const float*  point_rates = (const float*)d_in[0];   // (B, NS)
    const float*  spatial     = (const float*)d_in[1];   // (B, 2, H, W)
    const float*  gia         = (const float*)d_in[2];   // (B, H, W)
    const float2* coords      = (const float2*)d_in[3];  // (NS, 2)
    float* out = (float*)d_out;                          // (B, 1, H, W)

    // Per-batch min/max partials + output zeroing (no memset node)
    dim3 mg(SEGS, BB);
    minmax_kernel<<<mg, 256>>>(spatial, (float4*)out);

    // Scatter-add of masked rates
    dim3 sg(NS / (TPB * IT), BB);
    scatter_kernel<<<sg, TPB>>>(point_rates, coords, out);

    // Finalize: multiply by gia
    const int n4 = (BB * HWSZ) / 4;
    mul_kernel<<<n4 / (MTPB * MIT), MTPB>>>((const float4*)gia, (float4*)out, n4);
}